// round 2
// baseline (speedup 1.0000x reference)
#include <cuda_runtime.h>
#include <math.h>

#define BB 512
#define DD 768
#define HH 384
#define TK 16

// Scratch (__device__ globals: allocation-free rule), 16B aligned.
__device__ __align__(16) float g_buf_h[2][BB * HH];   // hidden activations (mu, lv)
__device__ __align__(16) float g_buf_o[2][BB * DD];   // mu, logvar outputs
__device__ __align__(16) float g_Syp[4][DD];          // y col-sum partials (4 row chunks)
__device__ __align__(16) float g_Sy2p[4][DD];
__device__ __align__(16) float g_Sy[DD];
__device__ __align__(16) float g_Sy2[DD];
__device__ double g_acc[2];                           // pos_sum, neg_sum
__device__ unsigned g_done;

// ---------------------------------------------------------------------------
// Helpers
// ---------------------------------------------------------------------------
__device__ __forceinline__ void cp_async16(void* smem, const void* gmem) {
    unsigned s = (unsigned)__cvta_generic_to_shared(smem);
    asm volatile("cp.async.cg.shared.global [%0], [%1], 16;\n" :: "r"(s), "l"(gmem));
}
__device__ __forceinline__ void cp_async_commit() {
    asm volatile("cp.async.commit_group;\n" ::: "memory");
}
__device__ __forceinline__ void cp_async_wait_all() {
    asm volatile("cp.async.wait_group 0;\n" ::: "memory");
}
// Packed fp32x2 FMA (sm_100+): c = a*b + c elementwise on two packed floats.
#define FMA2(c, a, b) asm("fma.rn.f32x2 %0, %1, %2, %0;" : "+l"(c) : "l"(a), "l"(b))

__device__ __forceinline__ float2 unpack2(unsigned long long v) {
    return make_float2(__uint_as_float((unsigned)v),
                       __uint_as_float((unsigned)(v >> 32)));
}

// ---------------------------------------------------------------------------
// Pipelined f32x2 GEMM: C[M,N] = act(A[M,K] @ W[K,N] + bias)
//   STAGE 1: A = X, C = g_buf_h[z], ReLU.  Extra z==2 slice: ystats + acc init.
//   STAGE 2: A = g_buf_h[z], C = g_buf_o[z], tanh on z==1. Extra z==2: Sy combine.
// Tile: TMv x 64, K slab 16, 256 threads. Micro-tile (TMv/16) x 4 per thread.
// A is stored duplicated as float2 (a,a) in smem so packed FMAs need no movs.
// ---------------------------------------------------------------------------
template <int TMv, int N, int K, int STAGE>
__global__ void __launch_bounds__(256)
mlp_gemm(const float* __restrict__ Xin, const float* __restrict__ Y,
         const float* __restrict__ W0, const float* __restrict__ W1,
         const float* __restrict__ bias0, const float* __restrict__ bias1)
{
    constexpr int MICRO_M = TMv / 16;
    constexpr int A_THREADS = TMv * 4;       // threads loading the A tile
    const int tid = threadIdx.x;
    const int z = blockIdx.z;

    if (z == 2) {
        // ---- fused side work (no smem / syncs touched) ----
        const int b = blockIdx.y * gridDim.x + blockIdx.x;
        if (STAGE == 1) {
            if (b < 12) {                     // ystats partials: 4 row chunks x 3 col blocks
                const int rc = b / 3, cb = b % 3;
                const int d = cb * 256 + tid;
                float s = 0.0f, s2 = 0.0f;
                const int j0 = rc * 128;
                #pragma unroll 4
                for (int j = j0; j < j0 + 128; j++) {
                    float v = Y[j * DD + d];
                    s += v;
                    s2 = fmaf(v, v, s2);
                }
                g_Syp[rc][d] = s;
                g_Sy2p[rc][d] = s2;
            } else if (b == 12 && tid == 0) {
                g_acc[0] = 0.0; g_acc[1] = 0.0; g_done = 0u;
            }
        } else {
            if (b < 3) {                      // combine Sy partials
                const int d = b * 256 + tid;
                g_Sy[d]  = (g_Syp[0][d] + g_Syp[1][d]) + (g_Syp[2][d] + g_Syp[3][d]);
                g_Sy2[d] = (g_Sy2p[0][d] + g_Sy2p[1][d]) + (g_Sy2p[2][d] + g_Sy2p[3][d]);
            }
        }
        return;
    }

    const float* __restrict__ A    = (STAGE == 1) ? Xin : g_buf_h[z];
    const float* __restrict__ W    = z ? W1 : W0;
    const float* __restrict__ bias = z ? bias1 : bias0;
    float* __restrict__ C          = (STAGE == 1) ? g_buf_h[z] : g_buf_o[z];

    __shared__ float2 As[2][TK][TMv];        // duplicated (a,a) pairs
    __shared__ float  Bs[2][TK][64];

    const int tx = tid & 15;                 // column group (4 cols)
    const int ty = tid >> 4;                 // row group (MICRO_M rows)
    const int rowBase = blockIdx.y * TMv;
    const int colBase = blockIdx.x * 64;

    // global load mapping
    const int ar = tid >> 2;                 // A row within tile
    const int ac = (tid & 3) * 4;            // A col (k offset)
    const int br = tid >> 4;                 // W row (k offset)
    const int bc = (tid & 15) * 4;           // W col

    const float* Aptr = A + (rowBase + ar) * K + ac;
    const float* Wptr = W + br * N + colBase + bc;

    // ---- preload tile 0 ----
    cp_async16(&Bs[0][br][bc], Wptr);
    cp_async_commit();
    if (tid < A_THREADS) {
        float4 a0 = *(const float4*)Aptr;
        As[0][ac + 0][ar] = make_float2(a0.x, a0.x);
        As[0][ac + 1][ar] = make_float2(a0.y, a0.y);
        As[0][ac + 2][ar] = make_float2(a0.z, a0.z);
        As[0][ac + 3][ar] = make_float2(a0.w, a0.w);
    }

    unsigned long long acc[MICRO_M][2];
    #pragma unroll
    for (int m = 0; m < MICRO_M; m++) { acc[m][0] = 0ull; acc[m][1] = 0ull; }

    constexpr int NT = K / TK;
    #pragma unroll 2
    for (int kt = 0; kt < NT; kt++) {
        const int cur = kt & 1, nxt = cur ^ 1;
        cp_async_wait_all();
        __syncthreads();

        const bool has = (kt + 1 < NT);
        float4 an;
        if (has) {
            if (tid < A_THREADS) an = *(const float4*)(Aptr + (kt + 1) * TK);
            cp_async16(&Bs[nxt][br][bc], Wptr + (size_t)(kt + 1) * TK * N);
            cp_async_commit();
        }

        #pragma unroll
        for (int kk = 0; kk < TK; kk++) {
            const ulonglong2* ap =
                reinterpret_cast<const ulonglong2*>(&As[cur][kk][ty * MICRO_M]);
            const ulonglong2 bv =
                *reinterpret_cast<const ulonglong2*>(&Bs[cur][kk][tx * 4]);
            #pragma unroll
            for (int mh = 0; mh < MICRO_M / 2; mh++) {
                ulonglong2 av = ap[mh];
                FMA2(acc[2 * mh + 0][0], av.x, bv.x);
                FMA2(acc[2 * mh + 0][1], av.x, bv.y);
                FMA2(acc[2 * mh + 1][0], av.y, bv.x);
                FMA2(acc[2 * mh + 1][1], av.y, bv.y);
            }
        }

        if (has && tid < A_THREADS) {
            As[nxt][ac + 0][ar] = make_float2(an.x, an.x);
            As[nxt][ac + 1][ar] = make_float2(an.y, an.y);
            As[nxt][ac + 2][ar] = make_float2(an.z, an.z);
            As[nxt][ac + 3][ar] = make_float2(an.w, an.w);
        }
    }

    // ---- epilogue ----
    const float4 bv4 = *(const float4*)&bias[colBase + tx * 4];
    #pragma unroll
    for (int m = 0; m < MICRO_M; m++) {
        const int row = rowBase + ty * MICRO_M + m;
        float2 c01 = unpack2(acc[m][0]);
        float2 c23 = unpack2(acc[m][1]);
        float4 o = make_float4(c01.x + bv4.x, c01.y + bv4.y,
                               c23.x + bv4.z, c23.y + bv4.w);
        if (STAGE == 1) {
            o.x = fmaxf(o.x, 0.0f); o.y = fmaxf(o.y, 0.0f);
            o.z = fmaxf(o.z, 0.0f); o.w = fmaxf(o.w, 0.0f);
        } else if (z == 1) {
            o.x = tanhf(o.x); o.y = tanhf(o.y);
            o.z = tanhf(o.z); o.w = tanhf(o.w);
        }
        *(float4*)&C[row * N + colBase + tx * 4] = o;
    }
}

// ---------------------------------------------------------------------------
// Closed-form reduction + finalize (last block):
//   pos: -(mu-y)^2/2 * e^{-lv} - lv/2
//   neg (summed over j analytically via y column moments):
//        -e^{-lv}/2 * (Sy2 - 2 mu Sy + B mu^2) - B lv / 2
//   result = pos/B - neg/B^2 - log1p(e^{-20}/(B-1))
// ---------------------------------------------------------------------------
__global__ void __launch_bounds__(256)
reduce_final(const float* __restrict__ y, float* __restrict__ out)
{
    const int T = gridDim.x * blockDim.x;
    double pos = 0.0, neg = 0.0;

    for (int t = blockIdx.x * blockDim.x + threadIdx.x; t < BB * DD; t += T) {
        const int d = t % DD;
        const float mu = g_buf_o[0][t];
        const float lv = g_buf_o[1][t];
        const float iv = __expf(-lv);
        const float yv = y[t];
        const float dm = mu - yv;
        pos += (double)fmaf(-0.5f * dm * dm, iv, -0.5f * lv);
        const float q = fmaf(fmaf((float)BB, mu, -2.0f * g_Sy[d]), mu, g_Sy2[d]);
        neg += (double)(-0.5f * iv * q - (0.5f * (float)BB) * lv);
    }

    __shared__ double sp[256];
    __shared__ double sn[256];
    const int tid = threadIdx.x;
    sp[tid] = pos;
    sn[tid] = neg;
    __syncthreads();
    for (int off = 128; off > 0; off >>= 1) {
        if (tid < off) { sp[tid] += sp[tid + off]; sn[tid] += sn[tid + off]; }
        __syncthreads();
    }
    if (tid == 0) {
        atomicAdd(&g_acc[0], sp[0]);
        atomicAdd(&g_acc[1], sn[0]);
        __threadfence();
        unsigned old = atomicAdd(&g_done, 1u);
        if (old == gridDim.x - 1) {
            g_done = 0u;
            double p = atomicAdd(&g_acc[0], 0.0);   // atomic read: latest L2 value
            double n = atomicAdd(&g_acc[1], 0.0);
            const double Cc = log1p(exp(-20.0) / (double)(BB - 1));
            out[0] = (float)(p / (double)BB - n / ((double)BB * (double)BB) - Cc);
        }
    }
}

// ---------------------------------------------------------------------------
// Launch: 3 kernels total.
// ---------------------------------------------------------------------------
extern "C" void kernel_launch(void* const* d_in, const int* in_sizes, int n_in,
                              void* d_out, int out_size)
{
    const float* x     = (const float*)d_in[0];
    const float* y     = (const float*)d_in[1];
    const float* mu_w1 = (const float*)d_in[2];
    const float* mu_b1 = (const float*)d_in[3];
    const float* mu_w2 = (const float*)d_in[4];
    const float* mu_b2 = (const float*)d_in[5];
    const float* lv_w1 = (const float*)d_in[6];
    const float* lv_b1 = (const float*)d_in[7];
    const float* lv_w2 = (const float*)d_in[8];
    const float* lv_b2 = (const float*)d_in[9];
    float* out = (float*)d_out;

    // Stage 1: hidden = relu(x @ w1 + b1)  [512x384, K=768], tiles 32x64.
    //          z==2 slice: y column-moment partials + accumulator init.
    mlp_gemm<32, HH, DD, 1><<<dim3(HH / 64, BB / 32, 3), 256>>>(
        x, y, mu_w1, lv_w1, mu_b1, lv_b1);

    // Stage 2: out = hidden @ w2 + b2 (tanh on lv path) [512x768, K=384], 64x64.
    //          z==2 slice: combine Sy partials.
    mlp_gemm<64, DD, HH, 2><<<dim3(DD / 64, BB / 64, 3), 256>>>(
        nullptr, y, mu_w2, lv_w2, mu_b2, lv_b2);

    // Closed-form reduction + finalize.
    reduce_final<<<232, 256>>>(y, out);
}

// round 4
// speedup vs baseline: 1.6419x; 1.6419x over previous
#include <cuda_runtime.h>
#include <math.h>

#define BB 512
#define DD 768
#define HH 384
#define TK 16

// -------------------- device scratch (allocation-free rule) -----------------
__device__ __align__(16) float g_part1[6 * 2 * BB * HH];  // stage1 split-K partials
__device__ __align__(16) float g_part2[3 * 2 * BB * DD];  // stage2 split-K partials
__device__ __align__(16) float g_h[2][BB * HH];           // relu(x@w1+b1)
__device__ __align__(16) float g_Syp[4][DD];
__device__ __align__(16) float g_Sy2p[4][DD];
__device__ __align__(16) float g_Sy[DD];
__device__ __align__(16) float g_Sy2[DD];
__device__ double g_acc[2];
__device__ unsigned g_done;

// -------------------- helpers ----------------------------------------------
__device__ __forceinline__ void cp_async16(void* smem, const void* gmem) {
    unsigned s = (unsigned)__cvta_generic_to_shared(smem);
    asm volatile("cp.async.cg.shared.global [%0], [%1], 16;\n" :: "r"(s), "l"(gmem));
}
__device__ __forceinline__ void cp_async_commit() {
    asm volatile("cp.async.commit_group;\n" ::: "memory");
}
__device__ __forceinline__ void cp_async_wait_all() {
    asm volatile("cp.async.wait_group 0;\n" ::: "memory");
}
// packed fp32x2 FMA: c += a*b (elementwise on 2 packed floats)
#define FMA2(c, a, b) asm("fma.rn.f32x2 %0, %1, %2, %0;" : "+l"(c) : "l"(a), "l"(b))

__device__ __forceinline__ float2 unpack2(unsigned long long v) {
    return make_float2(__uint_as_float((unsigned)v),
                       __uint_as_float((unsigned)(v >> 32)));
}

// ---------------------------------------------------------------------------
// Split-K GEMM, 128x128 CTA tile, 256 threads, 8x8 micro-tile (f32x2 packed).
//   C_part[s][z] = A_z[128 rows] @ W_z[K-chunk s]        (no bias/activation)
// STAGE==1: A_z = X (both paths), W = mu_w1/lv_w1, out g_part1. N=384,K=768,SK=6.
//           blockIdx.y >= MT*SK -> ystats partial blocks.
// STAGE==2: A_z = g_h[z],        W = mu_w2/lv_w2, out g_part2. N=768,K=384,SK=3.
// K-chunk per CTA = K/SK = 128 = 8 slabs of TK=16.
// ---------------------------------------------------------------------------
template <int N, int K, int SK, int STAGE>
__global__ void __launch_bounds__(256, 1)
gemm_splitk(const float* __restrict__ X, const float* __restrict__ Y,
            const float* __restrict__ W0, const float* __restrict__ W1)
{
    constexpr int MT = BB / 128;            // 4 row tiles
    constexpr int NSLAB = (K / SK) / TK;    // 8
    const int tid = threadIdx.x;
    const int z = blockIdx.z;

    if (STAGE == 1 && blockIdx.y >= MT * SK) {
        // ---- fused ystats partials: 12 blocks = (rowchunk 0..3, colblock 0..2) ----
        const int idx = (blockIdx.y - MT * SK) * 6 + blockIdx.x * 2 + z;
        if (idx < 12) {
            const int cb = idx % 3, rc = idx / 3;
            const int d = cb * 256 + tid;
            float s = 0.0f, s2 = 0.0f;
            const int j0 = rc * 128;
            #pragma unroll 4
            for (int j = j0; j < j0 + 128; j++) {
                float v = Y[j * DD + d];
                s += v;
                s2 = fmaf(v, v, s2);
            }
            g_Syp[rc][d] = s;
            g_Sy2p[rc][d] = s2;
        }
        return;
    }

    const int mTile = blockIdx.y % MT;
    const int s     = blockIdx.y / MT;
    const int rowBase = mTile * 128;
    const int colBase = blockIdx.x * 128;
    const int kBase   = s * (K / SK);

    const float* __restrict__ A = (STAGE == 1) ? X : g_h[z];
    const float* __restrict__ W = z ? W1 : W0;
    float* __restrict__ C = (STAGE == 1)
        ? (g_part1 + (size_t)(s * 2 + z) * (BB * HH))
        : (g_part2 + (size_t)(s * 2 + z) * (BB * DD));

    __shared__ __align__(16) float2 As[2][TK][128];  // duplicated (a,a), 32 KB
    __shared__ __align__(16) float  Bs[2][TK][128];  // 16 KB

    const int tx = tid & 15;
    const int ty = tid >> 4;

    // global load mapping (2 float4 each for A and B per slab)
    const int ar  = tid >> 2;            // A rows 0..63
    const int ac  = (tid & 3) * 4;       // A k-offset
    const int ar2 = ar + 64;             // A rows 64..127
    const int br  = tid >> 5;            // B k-rows 0..7
    const int bc  = (tid & 31) * 4;
    const int br2 = br + 8;              // B k-rows 8..15

    const float* Ap1 = A + (size_t)(rowBase + ar)  * K + kBase + ac;
    const float* Ap2 = A + (size_t)(rowBase + ar2) * K + kBase + ac;
    const float* Wp1 = W + (size_t)(kBase + br)  * N + colBase + bc;
    const float* Wp2 = W + (size_t)(kBase + br2) * N + colBase + bc;

    // ---- preload slab 0 ----
    cp_async16(&Bs[0][br][bc],  Wp1);
    cp_async16(&Bs[0][br2][bc], Wp2);
    cp_async_commit();
    {
        float4 a1 = *(const float4*)Ap1;
        float4 a2 = *(const float4*)Ap2;
        As[0][ac + 0][ar]  = make_float2(a1.x, a1.x);
        As[0][ac + 1][ar]  = make_float2(a1.y, a1.y);
        As[0][ac + 2][ar]  = make_float2(a1.z, a1.z);
        As[0][ac + 3][ar]  = make_float2(a1.w, a1.w);
        As[0][ac + 0][ar2] = make_float2(a2.x, a2.x);
        As[0][ac + 1][ar2] = make_float2(a2.y, a2.y);
        As[0][ac + 2][ar2] = make_float2(a2.z, a2.z);
        As[0][ac + 3][ar2] = make_float2(a2.w, a2.w);
    }

    unsigned long long acc[8][4];
    #pragma unroll
    for (int m = 0; m < 8; m++)
        #pragma unroll
        for (int p = 0; p < 4; p++) acc[m][p] = 0ull;

    #pragma unroll 1
    for (int kt = 0; kt < NSLAB; kt++) {
        const int cur = kt & 1, nxt = cur ^ 1;
        cp_async_wait_all();
        __syncthreads();

        const bool has = (kt + 1 < NSLAB);
        float4 a1n, a2n;
        if (has) {
            a1n = *(const float4*)(Ap1 + (kt + 1) * TK);
            a2n = *(const float4*)(Ap2 + (kt + 1) * TK);
            cp_async16(&Bs[nxt][br][bc],  Wp1 + (size_t)(kt + 1) * TK * N);
            cp_async16(&Bs[nxt][br2][bc], Wp2 + (size_t)(kt + 1) * TK * N);
            cp_async_commit();
        }

        #pragma unroll
        for (int kk = 0; kk < TK; kk++) {
            const ulonglong2* ap = (const ulonglong2*)&As[cur][kk][ty * 8];
            const ulonglong2* bp = (const ulonglong2*)&Bs[cur][kk][tx * 8];
            const ulonglong2 av01 = ap[0], av23 = ap[1], av45 = ap[2], av67 = ap[3];
            const ulonglong2 bv03 = bp[0], bv47 = bp[1];
            FMA2(acc[0][0], av01.x, bv03.x); FMA2(acc[0][1], av01.x, bv03.y);
            FMA2(acc[0][2], av01.x, bv47.x); FMA2(acc[0][3], av01.x, bv47.y);
            FMA2(acc[1][0], av01.y, bv03.x); FMA2(acc[1][1], av01.y, bv03.y);
            FMA2(acc[1][2], av01.y, bv47.x); FMA2(acc[1][3], av01.y, bv47.y);
            FMA2(acc[2][0], av23.x, bv03.x); FMA2(acc[2][1], av23.x, bv03.y);
            FMA2(acc[2][2], av23.x, bv47.x); FMA2(acc[2][3], av23.x, bv47.y);
            FMA2(acc[3][0], av23.y, bv03.x); FMA2(acc[3][1], av23.y, bv03.y);
            FMA2(acc[3][2], av23.y, bv47.x); FMA2(acc[3][3], av23.y, bv47.y);
            FMA2(acc[4][0], av45.x, bv03.x); FMA2(acc[4][1], av45.x, bv03.y);
            FMA2(acc[4][2], av45.x, bv47.x); FMA2(acc[4][3], av45.x, bv47.y);
            FMA2(acc[5][0], av45.y, bv03.x); FMA2(acc[5][1], av45.y, bv03.y);
            FMA2(acc[5][2], av45.y, bv47.x); FMA2(acc[5][3], av45.y, bv47.y);
            FMA2(acc[6][0], av67.x, bv03.x); FMA2(acc[6][1], av67.x, bv03.y);
            FMA2(acc[6][2], av67.x, bv47.x); FMA2(acc[6][3], av67.x, bv47.y);
            FMA2(acc[7][0], av67.y, bv03.x); FMA2(acc[7][1], av67.y, bv03.y);
            FMA2(acc[7][2], av67.y, bv47.x); FMA2(acc[7][3], av67.y, bv47.y);
        }

        if (has) {
            As[nxt][ac + 0][ar]  = make_float2(a1n.x, a1n.x);
            As[nxt][ac + 1][ar]  = make_float2(a1n.y, a1n.y);
            As[nxt][ac + 2][ar]  = make_float2(a1n.z, a1n.z);
            As[nxt][ac + 3][ar]  = make_float2(a1n.w, a1n.w);
            As[nxt][ac + 0][ar2] = make_float2(a2n.x, a2n.x);
            As[nxt][ac + 1][ar2] = make_float2(a2n.y, a2n.y);
            As[nxt][ac + 2][ar2] = make_float2(a2n.z, a2n.z);
            As[nxt][ac + 3][ar2] = make_float2(a2n.w, a2n.w);
        }
    }

    // ---- epilogue: raw partials, vectorized ----
    #pragma unroll
    for (int m = 0; m < 8; m++) {
        const int row = rowBase + ty * 8 + m;
        float2 c0 = unpack2(acc[m][0]);
        float2 c1 = unpack2(acc[m][1]);
        float2 c2 = unpack2(acc[m][2]);
        float2 c3 = unpack2(acc[m][3]);
        float* crow = C + (size_t)row * N + colBase + tx * 8;
        *(float4*)(crow)     = make_float4(c0.x, c0.y, c1.x, c1.y);
        *(float4*)(crow + 4) = make_float4(c2.x, c2.y, c3.x, c3.y);
    }
}

// ---------------------------------------------------------------------------
// combine1: g_h[z] = relu(sum_s g_part1[s][z] + b1);  plus Sy final + acc init
// grid: dim3(97, 2).  bx<96: combine (each thread 2 float4).  bx==96: side work.
// ---------------------------------------------------------------------------
__global__ void __launch_bounds__(256)
combine1(const float* __restrict__ mu_b1, const float* __restrict__ lv_b1)
{
    const int z = blockIdx.y;
    const int bx = blockIdx.x;
    const int tid = threadIdx.x;

    if (bx == 96) {
        if (z == 0) {
            #pragma unroll
            for (int j = 0; j < 3; j++) {
                const int d = j * 256 + tid;
                g_Sy[d]  = (g_Syp[0][d] + g_Syp[1][d]) + (g_Syp[2][d] + g_Syp[3][d]);
                g_Sy2[d] = (g_Sy2p[0][d] + g_Sy2p[1][d]) + (g_Sy2p[2][d] + g_Sy2p[3][d]);
            }
        } else if (tid == 0) {
            g_acc[0] = 0.0; g_acc[1] = 0.0; g_done = 0u;
        }
        return;
    }

    const float* __restrict__ bias = z ? lv_b1 : mu_b1;
    const size_t PH = (size_t)BB * HH;          // 196608 floats per path
    #pragma unroll
    for (int i = 0; i < 2; i++) {
        const int idx4 = bx * 512 + i * 256 + tid;      // float4 index < 49152
        const int n4 = idx4 % (HH / 4);
        const float4 b4 = *(const float4*)&bias[n4 * 4];
        const float4* p = (const float4*)g_part1;
        float4 s = p[(size_t)(0 * 2 + z) * (PH / 4) + idx4];
        #pragma unroll
        for (int sk = 1; sk < 6; sk++) {
            float4 v = p[(size_t)(sk * 2 + z) * (PH / 4) + idx4];
            s.x += v.x; s.y += v.y; s.z += v.z; s.w += v.w;
        }
        float4 o = make_float4(fmaxf(s.x + b4.x, 0.0f), fmaxf(s.y + b4.y, 0.0f),
                               fmaxf(s.z + b4.z, 0.0f), fmaxf(s.w + b4.w, 0.0f));
        ((float4*)g_h[z])[idx4] = o;
    }
}

// ---------------------------------------------------------------------------
// reduce_final: combine stage-2 partials (+bias, tanh), then closed-form sums:
//   pos: -(mu-y)^2/2 * e^{-lv} - lv/2
//   neg: -e^{-lv}/2 * (Sy2 - 2 mu Sy + B mu^2) - B lv / 2
//   out = pos/B - neg/B^2 - log1p(e^{-20}/(B-1))
// ---------------------------------------------------------------------------
__global__ void __launch_bounds__(256)
reduce_final(const float* __restrict__ y,
             const float* __restrict__ mu_b2, const float* __restrict__ lv_b2,
             float* __restrict__ out)
{
    const int tid = threadIdx.x;
    const size_t PD = (size_t)BB * DD;
    double pos = 0.0, neg = 0.0;

    for (int row = blockIdx.x; row < BB; row += gridDim.x) {
        #pragma unroll
        for (int j = 0; j < 3; j++) {
            const int d = j * 256 + tid;
            const size_t t = (size_t)row * DD + d;
            const float mu = (g_part2[0 * PD + t] + g_part2[2 * PD + t])
                           + g_part2[4 * PD + t] + mu_b2[d];
            const float lv = tanhf((g_part2[1 * PD + t] + g_part2[3 * PD + t])
                           + g_part2[5 * PD + t] + lv_b2[d]);
            const float iv = __expf(-lv);
            const float dm = mu - y[t];
            pos += (double)fmaf(-0.5f * dm * dm, iv, -0.5f * lv);
            const float q = fmaf(fmaf((float)BB, mu, -2.0f * g_Sy[d]), mu, g_Sy2[d]);
            neg += (double)(-0.5f * iv * q - (0.5f * (float)BB) * lv);
        }
    }

    __shared__ double sp[256];
    __shared__ double sn[256];
    sp[tid] = pos;
    sn[tid] = neg;
    __syncthreads();
    for (int off = 128; off > 0; off >>= 1) {
        if (tid < off) { sp[tid] += sp[tid + off]; sn[tid] += sn[tid + off]; }
        __syncthreads();
    }
    if (tid == 0) {
        atomicAdd(&g_acc[0], sp[0]);
        atomicAdd(&g_acc[1], sn[0]);
        __threadfence();
        unsigned old = atomicAdd(&g_done, 1u);
        if (old == gridDim.x - 1) {
            g_done = 0u;
            double p = atomicAdd(&g_acc[0], 0.0);
            double n = atomicAdd(&g_acc[1], 0.0);
            const double Cc = log1p(exp(-20.0) / (double)(BB - 1));
            out[0] = (float)(p / (double)BB - n / ((double)BB * (double)BB) - Cc);
        }
    }
}

// g_part2 layout: [s][z] flattened as (s*2+z); 0,2,4 are mu; 1,3,5 are lv.

// ---------------------------------------------------------------------------
// Launch: 4 kernels.
// ---------------------------------------------------------------------------
extern "C" void kernel_launch(void* const* d_in, const int* in_sizes, int n_in,
                              void* d_out, int out_size)
{
    const float* x     = (const float*)d_in[0];
    const float* y     = (const float*)d_in[1];
    const float* mu_w1 = (const float*)d_in[2];
    const float* mu_b1 = (const float*)d_in[3];
    const float* mu_w2 = (const float*)d_in[4];
    const float* mu_b2 = (const float*)d_in[5];
    const float* lv_w1 = (const float*)d_in[6];
    const float* lv_b1 = (const float*)d_in[7];
    const float* lv_w2 = (const float*)d_in[8];
    const float* lv_b2 = (const float*)d_in[9];
    float* out = (float*)d_out;

    // Stage 1: partials of x @ w1  [512x384, K=768, split-K 6] + ystats blocks
    gemm_splitk<HH, DD, 6, 1><<<dim3(3, 26, 2), 256>>>(x, y, mu_w1, lv_w1);

    // combine + bias + relu -> g_h ; Sy final ; acc init
    combine1<<<dim3(97, 2), 256>>>(mu_b1, lv_b1);

    // Stage 2: partials of g_h @ w2 [512x768, K=384, split-K 3]
    gemm_splitk<DD, HH, 3, 2><<<dim3(6, 12, 2), 256>>>(nullptr, y, mu_w2, lv_w2);

    // combine stage-2 partials + bias + tanh + closed-form reduction
    reduce_final<<<148, 256>>>(y, mu_b2, lv_b2, out);
}

// round 5
// speedup vs baseline: 1.6534x; 1.0070x over previous
#include <cuda_runtime.h>
#include <math.h>

#define BB 512
#define DD 768
#define HH 384
#define TK 16

// -------------------- device scratch (allocation-free rule) -----------------
__device__ __align__(16) float g_part1[6 * 2 * BB * HH];  // stage1 split-K partials
__device__ __align__(16) float g_part2[3 * 2 * BB * DD];  // stage2 split-K partials
__device__ __align__(16) float g_Syp[4][DD];
__device__ __align__(16) float g_Sy2p[4][DD];
__device__ __align__(16) float g_Sy[DD];
__device__ __align__(16) float g_Sy2[DD];
__device__ double g_acc[2];
__device__ unsigned g_done;

// -------------------- helpers ----------------------------------------------
__device__ __forceinline__ void cp_async16(void* smem, const void* gmem) {
    unsigned s = (unsigned)__cvta_generic_to_shared(smem);
    asm volatile("cp.async.cg.shared.global [%0], [%1], 16;\n" :: "r"(s), "l"(gmem));
}
__device__ __forceinline__ void cp_async_commit() {
    asm volatile("cp.async.commit_group;\n" ::: "memory");
}
__device__ __forceinline__ void cp_async_wait_all() {
    asm volatile("cp.async.wait_group 0;\n" ::: "memory");
}
// packed fp32x2 FMA: c += a*b (elementwise on 2 packed floats)
#define FMA2(c, a, b) asm("fma.rn.f32x2 %0, %1, %2, %0;" : "+l"(c) : "l"(a), "l"(b))

__device__ __forceinline__ float2 unpack2(unsigned long long v) {
    return make_float2(__uint_as_float((unsigned)v),
                       __uint_as_float((unsigned)(v >> 32)));
}

// ---------------------------------------------------------------------------
// Split-K GEMM, 128x128 CTA tile, 256 threads, 8x8 micro-tile (f32x2 packed).
//   C_part[s][z] = A_z[128 rows] @ W_z[K-chunk s]        (no bias/activation)
// STAGE==1: A_z = X (both paths), W = mu_w1/lv_w1 -> g_part1. N=384,K=768,SK=6.
//           extra blocks (blockIdx.y >= MT*SK): ystats partials.
// STAGE==2: A_z = relu(sum_s g_part1[s][z] + b1)  (fused on the fly),
//           W = mu_w2/lv_w2 -> g_part2. N=768,K=384,SK=3.
//           extra blocks: Sy finalize + accumulator init.
// K-chunk per CTA = K/SK = 128 = 8 slabs of TK=16.
// ---------------------------------------------------------------------------
template <int N, int K, int SK, int STAGE>
__global__ void __launch_bounds__(256, 1)
gemm_splitk(const float* __restrict__ X, const float* __restrict__ Y,
            const float* __restrict__ W0, const float* __restrict__ W1,
            const float* __restrict__ mu_b1, const float* __restrict__ lv_b1)
{
    constexpr int MT = BB / 128;            // 4 row tiles
    constexpr int NSLAB = (K / SK) / TK;    // 8
    constexpr size_t PH = (size_t)BB * HH;
    const int tid = threadIdx.x;
    const int z = blockIdx.z;

    if (blockIdx.y >= MT * SK) {
        if (STAGE == 1) {
            // ---- fused ystats partials: 12 blocks = (rowchunk, colblock) ----
            const int idx = (blockIdx.y - MT * SK) * 6 + blockIdx.x * 2 + z;
            if (idx < 12) {
                const int cb = idx % 3, rc = idx / 3;
                const int d = cb * 256 + tid;
                float s = 0.0f, s2 = 0.0f;
                const int j0 = rc * 128;
                #pragma unroll 4
                for (int j = j0; j < j0 + 128; j++) {
                    float v = Y[j * DD + d];
                    s += v;
                    s2 = fmaf(v, v, s2);
                }
                g_Syp[rc][d] = s;
                g_Sy2p[rc][d] = s2;
            }
        } else {
            // ---- Sy finalize (z=0, bx<3) + acc init (z=1, bx=0) ----
            if (z == 0 && blockIdx.x < 3) {
                const int d = blockIdx.x * 256 + tid;
                g_Sy[d]  = (g_Syp[0][d] + g_Syp[1][d]) + (g_Syp[2][d] + g_Syp[3][d]);
                g_Sy2[d] = (g_Sy2p[0][d] + g_Sy2p[1][d]) + (g_Sy2p[2][d] + g_Sy2p[3][d]);
            } else if (z == 1 && blockIdx.x == 0 && tid == 0) {
                g_acc[0] = 0.0; g_acc[1] = 0.0; g_done = 0u;
            }
        }
        return;
    }

    const int mTile = blockIdx.y % MT;
    const int s     = blockIdx.y / MT;
    const int rowBase = mTile * 128;
    const int colBase = blockIdx.x * 128;
    const int kBase   = s * (K / SK);

    const float* __restrict__ W = z ? W1 : W0;
    const float* __restrict__ b1 = z ? lv_b1 : mu_b1;
    float* __restrict__ C = (STAGE == 1)
        ? (g_part1 + (size_t)(s * 2 + z) * (BB * HH))
        : (g_part2 + (size_t)(s * 2 + z) * ((size_t)BB * DD));

    __shared__ __align__(16) float2 As[2][TK][128];  // duplicated (a,a), 32 KB
    __shared__ __align__(16) float  Bs[2][TK][128];  // 16 KB

    const int tx = tid & 15;
    const int ty = tid >> 4;

    // global load mapping (2 float4 each for A and B per slab)
    const int ar  = tid >> 2;            // A rows 0..63
    const int ac  = (tid & 3) * 4;       // A k-offset
    const int ar2 = ar + 64;             // A rows 64..127
    const int br  = tid >> 5;            // B k-rows 0..7
    const int bc  = (tid & 31) * 4;
    const int br2 = br + 8;              // B k-rows 8..15

    const float* Wp1 = W + (size_t)(kBase + br)  * N + colBase + bc;
    const float* Wp2 = W + (size_t)(kBase + br2) * N + colBase + bc;
    const float* Ap1 = (STAGE == 1) ? X + (size_t)(rowBase + ar)  * K + kBase + ac : nullptr;
    const float* Ap2 = (STAGE == 1) ? X + (size_t)(rowBase + ar2) * K + kBase + ac : nullptr;

    // Fused A producer for stage 2: relu(sum of 6 stage-1 partials + b1)
    auto loadA = [&](int rowInTile, int kt) -> float4 {
        if (STAGE == 1) {
            return *(const float4*)((rowInTile == 0 ? Ap1 : Ap2) + kt * TK);
        } else {
            const int row  = rowBase + (rowInTile == 0 ? ar : ar2);
            const int koff = kBase + ac + kt * TK;
            const size_t t4 = ((size_t)row * HH + koff) >> 2;
            const float4* P = (const float4*)g_part1;
            const size_t q = PH >> 2;
            float4 s0 = P[(0 * 2 + z) * q + t4];
            float4 s1 = P[(1 * 2 + z) * q + t4];
            float4 s2 = P[(2 * 2 + z) * q + t4];
            float4 s3 = P[(3 * 2 + z) * q + t4];
            float4 s4 = P[(4 * 2 + z) * q + t4];
            float4 s5 = P[(5 * 2 + z) * q + t4];
            float4 bb = *(const float4*)&b1[koff];
            float4 r;
            r.x = fmaxf(((s0.x + s1.x) + (s2.x + s3.x)) + (s4.x + s5.x) + bb.x, 0.0f);
            r.y = fmaxf(((s0.y + s1.y) + (s2.y + s3.y)) + (s4.y + s5.y) + bb.y, 0.0f);
            r.z = fmaxf(((s0.z + s1.z) + (s2.z + s3.z)) + (s4.z + s5.z) + bb.z, 0.0f);
            r.w = fmaxf(((s0.w + s1.w) + (s2.w + s3.w)) + (s4.w + s5.w) + bb.w, 0.0f);
            return r;
        }
    };

    // ---- preload slab 0 ----
    cp_async16(&Bs[0][br][bc],  Wp1);
    cp_async16(&Bs[0][br2][bc], Wp2);
    cp_async_commit();
    {
        float4 a1 = loadA(0, 0);
        float4 a2 = loadA(1, 0);
        As[0][ac + 0][ar]  = make_float2(a1.x, a1.x);
        As[0][ac + 1][ar]  = make_float2(a1.y, a1.y);
        As[0][ac + 2][ar]  = make_float2(a1.z, a1.z);
        As[0][ac + 3][ar]  = make_float2(a1.w, a1.w);
        As[0][ac + 0][ar2] = make_float2(a2.x, a2.x);
        As[0][ac + 1][ar2] = make_float2(a2.y, a2.y);
        As[0][ac + 2][ar2] = make_float2(a2.z, a2.z);
        As[0][ac + 3][ar2] = make_float2(a2.w, a2.w);
    }

    unsigned long long acc[8][4];
    #pragma unroll
    for (int m = 0; m < 8; m++)
        #pragma unroll
        for (int p = 0; p < 4; p++) acc[m][p] = 0ull;

    #pragma unroll 1
    for (int kt = 0; kt < NSLAB; kt++) {
        const int cur = kt & 1, nxt = cur ^ 1;
        cp_async_wait_all();
        __syncthreads();

        const bool has = (kt + 1 < NSLAB);
        float4 a1n, a2n;
        if (has) {
            a1n = loadA(0, kt + 1);
            a2n = loadA(1, kt + 1);
            cp_async16(&Bs[nxt][br][bc],  Wp1 + (size_t)(kt + 1) * TK * N);
            cp_async16(&Bs[nxt][br2][bc], Wp2 + (size_t)(kt + 1) * TK * N);
            cp_async_commit();
        }

        #pragma unroll
        for (int kk = 0; kk < TK; kk++) {
            const ulonglong2* ap = (const ulonglong2*)&As[cur][kk][ty * 8];
            const ulonglong2* bp = (const ulonglong2*)&Bs[cur][kk][tx * 8];
            const ulonglong2 av01 = ap[0], av23 = ap[1], av45 = ap[2], av67 = ap[3];
            const ulonglong2 bv03 = bp[0], bv47 = bp[1];
            FMA2(acc[0][0], av01.x, bv03.x); FMA2(acc[0][1], av01.x, bv03.y);
            FMA2(acc[0][2], av01.x, bv47.x); FMA2(acc[0][3], av01.x, bv47.y);
            FMA2(acc[1][0], av01.y, bv03.x); FMA2(acc[1][1], av01.y, bv03.y);
            FMA2(acc[1][2], av01.y, bv47.x); FMA2(acc[1][3], av01.y, bv47.y);
            FMA2(acc[2][0], av23.x, bv03.x); FMA2(acc[2][1], av23.x, bv03.y);
            FMA2(acc[2][2], av23.x, bv47.x); FMA2(acc[2][3], av23.x, bv47.y);
            FMA2(acc[3][0], av23.y, bv03.x); FMA2(acc[3][1], av23.y, bv03.y);
            FMA2(acc[3][2], av23.y, bv47.x); FMA2(acc[3][3], av23.y, bv47.y);
            FMA2(acc[4][0], av45.x, bv03.x); FMA2(acc[4][1], av45.x, bv03.y);
            FMA2(acc[4][2], av45.x, bv47.x); FMA2(acc[4][3], av45.x, bv47.y);
            FMA2(acc[5][0], av45.y, bv03.x); FMA2(acc[5][1], av45.y, bv03.y);
            FMA2(acc[5][2], av45.y, bv47.x); FMA2(acc[5][3], av45.y, bv47.y);
            FMA2(acc[6][0], av67.x, bv03.x); FMA2(acc[6][1], av67.x, bv03.y);
            FMA2(acc[6][2], av67.x, bv47.x); FMA2(acc[6][3], av67.x, bv47.y);
            FMA2(acc[7][0], av67.y, bv03.x); FMA2(acc[7][1], av67.y, bv03.y);
            FMA2(acc[7][2], av67.y, bv47.x); FMA2(acc[7][3], av67.y, bv47.y);
        }

        if (has) {
            As[nxt][ac + 0][ar]  = make_float2(a1n.x, a1n.x);
            As[nxt][ac + 1][ar]  = make_float2(a1n.y, a1n.y);
            As[nxt][ac + 2][ar]  = make_float2(a1n.z, a1n.z);
            As[nxt][ac + 3][ar]  = make_float2(a1n.w, a1n.w);
            As[nxt][ac + 0][ar2] = make_float2(a2n.x, a2n.x);
            As[nxt][ac + 1][ar2] = make_float2(a2n.y, a2n.y);
            As[nxt][ac + 2][ar2] = make_float2(a2n.z, a2n.z);
            As[nxt][ac + 3][ar2] = make_float2(a2n.w, a2n.w);
        }
    }

    // ---- epilogue: raw partials, vectorized ----
    #pragma unroll
    for (int m = 0; m < 8; m++) {
        const int row = rowBase + ty * 8 + m;
        float2 c0 = unpack2(acc[m][0]);
        float2 c1 = unpack2(acc[m][1]);
        float2 c2 = unpack2(acc[m][2]);
        float2 c3 = unpack2(acc[m][3]);
        float* crow = C + (size_t)row * N + colBase + tx * 8;
        *(float4*)(crow)     = make_float4(c0.x, c0.y, c1.x, c1.y);
        *(float4*)(crow + 4) = make_float4(c2.x, c2.y, c3.x, c3.y);
    }
}

// ---------------------------------------------------------------------------
// reduce_final: one float4 per thread (384 blocks x 256 thr = BB*DD/4 exactly).
// Combines stage-2 partials (+bias, tanh) and does the closed-form sums:
//   pos: -(mu-y)^2/2 * e^{-lv} - lv/2
//   neg: -e^{-lv}/2 * (Sy2 - 2 mu Sy + B mu^2) - B lv / 2
//   out = pos/B - neg/B^2 - log1p(e^{-20}/(B-1))
// ---------------------------------------------------------------------------
__global__ void __launch_bounds__(256)
reduce_final(const float* __restrict__ y,
             const float* __restrict__ mu_b2, const float* __restrict__ lv_b2,
             float* __restrict__ out)
{
    const int tid = threadIdx.x;
    const int g = blockIdx.x * 256 + tid;          // float4 index, < 98304
    const int d4 = g % (DD / 4);

    constexpr size_t PD4 = (size_t)BB * DD / 4;
    const float4* P = (const float4*)g_part2;

    const float4 m0 = P[0 * PD4 + g];
    const float4 m1 = P[2 * PD4 + g];
    const float4 m2 = P[4 * PD4 + g];
    const float4 l0 = P[1 * PD4 + g];
    const float4 l1 = P[3 * PD4 + g];
    const float4 l2 = P[5 * PD4 + g];
    const float4 mb = ((const float4*)mu_b2)[d4];
    const float4 lb = ((const float4*)lv_b2)[d4];
    const float4 y4 = ((const float4*)y)[g];
    const float4 sy = ((const float4*)g_Sy)[d4];
    const float4 s2 = ((const float4*)g_Sy2)[d4];

    float mu[4]  = {m0.x + m1.x + m2.x + mb.x, m0.y + m1.y + m2.y + mb.y,
                    m0.z + m1.z + m2.z + mb.z, m0.w + m1.w + m2.w + mb.w};
    float lv[4]  = {tanhf(l0.x + l1.x + l2.x + lb.x), tanhf(l0.y + l1.y + l2.y + lb.y),
                    tanhf(l0.z + l1.z + l2.z + lb.z), tanhf(l0.w + l1.w + l2.w + lb.w)};
    float yv[4]  = {y4.x, y4.y, y4.z, y4.w};
    float Sy[4]  = {sy.x, sy.y, sy.z, sy.w};
    float Sy2[4] = {s2.x, s2.y, s2.z, s2.w};

    float posf = 0.0f, negf = 0.0f;
    #pragma unroll
    for (int i = 0; i < 4; i++) {
        const float iv = __expf(-lv[i]);
        const float dm = mu[i] - yv[i];
        posf += fmaf(-0.5f * dm * dm, iv, -0.5f * lv[i]);
        const float q = fmaf(fmaf((float)BB, mu[i], -2.0f * Sy[i]), mu[i], Sy2[i]);
        negf += fmaf(-0.5f * iv, q, -(0.5f * (float)BB) * lv[i]);
    }

    __shared__ double sp[256];
    __shared__ double sn[256];
    sp[tid] = (double)posf;
    sn[tid] = (double)negf;
    __syncthreads();
    for (int off = 128; off > 0; off >>= 1) {
        if (tid < off) { sp[tid] += sp[tid + off]; sn[tid] += sn[tid + off]; }
        __syncthreads();
    }
    if (tid == 0) {
        atomicAdd(&g_acc[0], sp[0]);
        atomicAdd(&g_acc[1], sn[0]);
        __threadfence();
        unsigned old = atomicAdd(&g_done, 1u);
        if (old == gridDim.x - 1) {
            g_done = 0u;
            double p = atomicAdd(&g_acc[0], 0.0);
            double n = atomicAdd(&g_acc[1], 0.0);
            const double Cc = log1p(exp(-20.0) / (double)(BB - 1));
            out[0] = (float)(p / (double)BB - n / ((double)BB * (double)BB) - Cc);
        }
    }
}

// g_part layouts: [s][z] flattened as (s*2+z); even = mu path, odd = lv path.

// ---------------------------------------------------------------------------
// Launch: 3 kernels.
// ---------------------------------------------------------------------------
extern "C" void kernel_launch(void* const* d_in, const int* in_sizes, int n_in,
                              void* d_out, int out_size)
{
    const float* x     = (const float*)d_in[0];
    const float* y     = (const float*)d_in[1];
    const float* mu_w1 = (const float*)d_in[2];
    const float* mu_b1 = (const float*)d_in[3];
    const float* mu_w2 = (const float*)d_in[4];
    const float* mu_b2 = (const float*)d_in[5];
    const float* lv_w1 = (const float*)d_in[6];
    const float* lv_b1 = (const float*)d_in[7];
    const float* lv_w2 = (const float*)d_in[8];
    const float* lv_b2 = (const float*)d_in[9];
    float* out = (float*)d_out;

    // Stage 1: partials of x @ w1  [512x384, K=768, split-K 6] + ystats blocks
    gemm_splitk<HH, DD, 6, 1><<<dim3(3, 26, 2), 256>>>(
        x, y, mu_w1, lv_w1, nullptr, nullptr);

    // Stage 2: partials of relu(sum+b1) @ w2 [512x768, K=384, split-K 3]
    //          + Sy finalize + acc init side blocks
    gemm_splitk<DD, HH, 3, 2><<<dim3(6, 13, 2), 256>>>(
        nullptr, y, mu_w2, lv_w2, mu_b1, lv_b1);

    // combine stage-2 partials + bias + tanh + closed-form reduction
    reduce_final<<<384, 256>>>(y, mu_b2, lv_b2, out);
}